// round 10
// baseline (speedup 1.0000x reference)
#include <cuda_runtime.h>
#include <cuda_bf16.h>
#include <cstdint>

typedef __nv_bfloat16  bf16;
typedef __nv_bfloat162 bf162;
typedef unsigned long long ull;

#define B_  8
#define NQ_ 256
#define NK_ 4096
#define C_  1024
#define H_  16
#define D_  64

// ---------------- scratch (static device globals) ---------------------------
__device__ bf16 g_qhi[(size_t)B_ * NQ_ * C_];
__device__ bf16 g_qlo[(size_t)B_ * NQ_ * C_];
__device__ bf16 g_ahi[(size_t)B_ * NK_ * C_];
__device__ bf16 g_alo[(size_t)B_ * NK_ * C_];
__device__ bf16 g_vhi[(size_t)B_ * NK_ * C_];
__device__ bf16 g_vlo[(size_t)B_ * NK_ * C_];
__device__ bf16 g_khi[(size_t)B_ * NK_ * C_];
__device__ bf16 g_klo[(size_t)B_ * NK_ * C_];
__device__ bf16 g_bhi[C_ * C_];
__device__ bf16 g_blo[C_ * C_];
__device__ float g_scores[(size_t)B_ * H_ * NQ_ * NK_];

// ---------------- helpers ----------------------------------------------------
__device__ __forceinline__ uint32_t smem_u32(const void* p) {
    uint32_t a;
    asm("{ .reg .u64 t; cvta.to.shared.u64 t, %1; cvt.u32.u64 %0, t; }"
        : "=r"(a) : "l"(p));
    return a;
}
__device__ __forceinline__ void ldsm4(uint32_t* r, uint32_t addr) {
    asm volatile("ldmatrix.sync.aligned.m8n8.x4.shared.b16 {%0,%1,%2,%3}, [%4];"
                 : "=r"(r[0]), "=r"(r[1]), "=r"(r[2]), "=r"(r[3]) : "r"(addr));
}
__device__ __forceinline__ void ldsm4t(uint32_t* r, uint32_t addr) {
    asm volatile("ldmatrix.sync.aligned.m8n8.x4.trans.shared.b16 {%0,%1,%2,%3}, [%4];"
                 : "=r"(r[0]), "=r"(r[1]), "=r"(r[2]), "=r"(r[3]) : "r"(addr));
}
__device__ __forceinline__ void mma16816(float* d, const uint32_t* a,
                                         uint32_t b0, uint32_t b1) {
    asm volatile(
        "mma.sync.aligned.m16n8k16.row.col.f32.bf16.bf16.f32 "
        "{%0,%1,%2,%3}, {%4,%5,%6,%7}, {%8,%9}, {%0,%1,%2,%3};"
        : "+f"(d[0]), "+f"(d[1]), "+f"(d[2]), "+f"(d[3])
        : "r"(a[0]), "r"(a[1]), "r"(a[2]), "r"(a[3]), "r"(b0), "r"(b1));
}
__device__ __forceinline__ void cp16(uint32_t s, const void* g) {
    asm volatile("cp.async.cg.shared.global [%0], [%1], 16;"
                 :: "r"(s), "l"(__cvta_generic_to_global(g)));
}
__device__ __forceinline__ void split_bf16(float x, bf16& h, bf16& l) {
    h = __float2bfloat16(x);
    l = __float2bfloat16(x - __bfloat162float(h));
}
__device__ __forceinline__ ull pack2(float x, float y) {
    ull r;
    asm("mov.b64 %0, {%1, %2};" : "=l"(r)
        : "r"(__float_as_uint(x)), "r"(__float_as_uint(y)));
    return r;
}
__device__ __forceinline__ float2 unpack2(ull v) {
    unsigned lo, hi;
    asm("mov.b64 {%0, %1}, %2;" : "=r"(lo), "=r"(hi) : "l"(v));
    return make_float2(__uint_as_float(lo), __uint_as_float(hi));
}
__device__ __forceinline__ ull fma2(ull a, ull b, ull c) {
    ull d;
    asm("fma.rn.f32x2 %0, %1, %2, %3;" : "=l"(d) : "l"(a), "l"(b), "l"(c));
    return d;
}
__device__ __forceinline__ ull add2(ull a, ull b) {
    ull d;
    asm("add.rn.f32x2 %0, %1, %2;" : "=l"(d) : "l"(a), "l"(b));
    return d;
}

// packed exp(0.125*s + b) on the FMA pipe via exp2 polynomial
__device__ __forceinline__ float2 exp_poly2(float s0, float s1, float b0, float b1) {
    const ull SCL2  = pack2(0.1803368801f, 0.1803368801f);   // 0.125*log2(e)
    const ull L2E2  = pack2(1.44269504f, 1.44269504f);
    const ull CBIG2 = pack2(12582912.f, 12582912.f);          // 1.5*2^23
    const ull CNEG2 = pack2(-12582912.f, -12582912.f);
    const ull NONE2 = pack2(-1.f, -1.f);
    const ull ONE2  = pack2(1.f, 1.f);
    const ull C4P   = pack2(0.0096181291f, 0.0096181291f);
    const ull C3P   = pack2(0.0555041087f, 0.0555041087f);
    const ull C2P   = pack2(0.2402265069f, 0.2402265069f);
    const ull C1P   = pack2(0.6931471806f, 0.6931471806f);
    ull t2 = fma2(pack2(s0, s1), SCL2, fma2(pack2(b0, b1), L2E2, 0ULL));
    ull m2 = add2(t2, CBIG2);
    ull n2 = add2(m2, CNEG2);
    ull f2 = fma2(n2, NONE2, t2);
    ull p2 = fma2(f2, C4P, C3P);
    p2 = fma2(f2, p2, C2P);
    p2 = fma2(f2, p2, C1P);
    p2 = fma2(f2, p2, ONE2);
    float2 mf = unpack2(m2);
    float2 pf = unpack2(p2);
    float e0 = __int_as_float(__float_as_int(pf.x) + (__float_as_int(mf.x) << 23));
    float e1 = __int_as_float(__float_as_int(pf.y) + (__float_as_int(mf.y) << 23));
    return make_float2(e0, e1);
}

// ---------------- LayerNorm core ---------------------------------------------
__device__ __forceinline__ float4 ln_row(const float* x, const float* w,
                                         const float* bw, size_t base, int t,
                                         float* rs, float* rs2) {
    float4 v = *(const float4*)(x + base + t * 4);
    float s  = v.x + v.y + v.z + v.w;
    float s2 = v.x * v.x + v.y * v.y + v.z * v.z + v.w * v.w;
    int lane = t & 31, wid = t >> 5;
#pragma unroll
    for (int o = 16; o > 0; o >>= 1) {
        s  += __shfl_xor_sync(0xffffffffu, s,  o);
        s2 += __shfl_xor_sync(0xffffffffu, s2, o);
    }
    if (lane == 0) { rs[wid] = s; rs2[wid] = s2; }
    __syncthreads();
    if (t == 0) {
        float a = 0.f, b = 0.f;
#pragma unroll
        for (int i = 0; i < 8; i++) { a += rs[i]; b += rs2[i]; }
        rs[0] = a; rs2[0] = b;
    }
    __syncthreads();
    float mu  = rs[0]  * (1.0f / C_);
    float var = rs2[0] * (1.0f / C_) - mu * mu;
    float inv = rsqrtf(var + 1e-5f);
    float4 wv = *(const float4*)(w  + t * 4);
    float4 bv = *(const float4*)(bw + t * 4);
    float4 o;
    o.x = (v.x - mu) * inv * wv.x + bv.x;
    o.y = (v.y - mu) * inv * wv.y + bv.y;
    o.z = (v.z - mu) * inv * wv.z + bv.z;
    o.w = (v.w - mu) * inv * wv.w + bv.w;
    return o;
}

__global__ __launch_bounds__(256) void ln_q_kernel(
    const float* __restrict__ x, const float* __restrict__ w,
    const float* __restrict__ bw, const float* __restrict__ pos,
    bf16* __restrict__ qhi, bf16* __restrict__ qlo)
{
    __shared__ float rs[8], rs2[8];
    int row = blockIdx.x, t = threadIdx.x;
    size_t base = (size_t)row * C_;
    float4 o = ln_row(x, w, bw, base, t, rs, rs2);
    float4 p = *(const float4*)(pos + base + t * 4);
    float a0 = o.x + p.x, a1 = o.y + p.y, a2 = o.z + p.z, a3 = o.w + p.w;
    bf16 h0, h1, h2, h3, l0, l1, l2, l3;
    split_bf16(a0, h0, l0); split_bf16(a1, h1, l1);
    split_bf16(a2, h2, l2); split_bf16(a3, h3, l3);
    *(bf162*)(qhi + base + t * 4)     = bf162(h0, h1);
    *(bf162*)(qhi + base + t * 4 + 2) = bf162(h2, h3);
    *(bf162*)(qlo + base + t * 4)     = bf162(l0, l1);
    *(bf162*)(qlo + base + t * 4 + 2) = bf162(l2, l3);
}

__global__ __launch_bounds__(256) void ln_k_kernel(
    const float* __restrict__ x, const float* __restrict__ w,
    const float* __restrict__ bw, const float* __restrict__ pos,
    bf16* __restrict__ vhi, bf16* __restrict__ vlo,
    bf16* __restrict__ ahi, bf16* __restrict__ alo)
{
    __shared__ float rs[8], rs2[8];
    int row = blockIdx.x, t = threadIdx.x;
    size_t base = (size_t)row * C_;
    float4 o = ln_row(x, w, bw, base, t, rs, rs2);

    bf16 h0, h1, h2, h3, l0, l1, l2, l3;
    split_bf16(o.x, h0, l0); split_bf16(o.y, h1, l1);
    split_bf16(o.z, h2, l2); split_bf16(o.w, h3, l3);
    *(bf162*)(vhi + base + t * 4)     = bf162(h0, h1);
    *(bf162*)(vhi + base + t * 4 + 2) = bf162(h2, h3);
    *(bf162*)(vlo + base + t * 4)     = bf162(l0, l1);
    *(bf162*)(vlo + base + t * 4 + 2) = bf162(l2, l3);

    float4 p = *(const float4*)(pos + base + t * 4);
    float a0 = o.x + p.x, a1 = o.y + p.y, a2 = o.z + p.z, a3 = o.w + p.w;
    split_bf16(a0, h0, l0); split_bf16(a1, h1, l1);
    split_bf16(a2, h2, l2); split_bf16(a3, h3, l3);
    *(bf162*)(ahi + base + t * 4)     = bf162(h0, h1);
    *(bf162*)(ahi + base + t * 4 + 2) = bf162(h2, h3);
    *(bf162*)(alo + base + t * 4)     = bf162(l0, l1);
    *(bf162*)(alo + base + t * 4 + 2) = bf162(l2, l3);
}

__global__ __launch_bounds__(256) void wconv_kernel(
    const float* __restrict__ Wk, bf16* __restrict__ hi, bf16* __restrict__ lo)
{
    size_t i = (size_t)blockIdx.x * 1024 + threadIdx.x * 4;
    float4 v = *(const float4*)(Wk + i);
    bf16 h0, h1, h2, h3, l0, l1, l2, l3;
    split_bf16(v.x, h0, l0); split_bf16(v.y, h1, l1);
    split_bf16(v.z, h2, l2); split_bf16(v.w, h3, l3);
    *(bf162*)(hi + i)     = bf162(h0, h1);
    *(bf162*)(hi + i + 2) = bf162(h2, h3);
    *(bf162*)(lo + i)     = bf162(l0, l1);
    *(bf162*)(lo + i + 2) = bf162(l2, l3);
}

// ---------------- K projection: mma.sync, cp.async 2-stage, 2 CTA/SM --------
#define KP_AH 0
#define KP_AL 10240
#define KP_BH 20480
#define KP_BL 30720
#define KP_STAGE 40960
#define KP_SMEM (2 * KP_STAGE)

__global__ __launch_bounds__(256, 2) void kproj_mma(
    const bf16* __restrict__ ahi_g, const bf16* __restrict__ alo_g,
    const bf16* __restrict__ bhi_g, const bf16* __restrict__ blo_g,
    bf16* __restrict__ khi_g, bf16* __restrict__ klo_g)
{
    extern __shared__ char sm[];
    uint32_t smb = smem_u32(sm);
    int tid = threadIdx.x, lane = tid & 31, wid = tid >> 5;
    int wm = wid >> 1, wn = wid & 1;
    int m0 = blockIdx.y * 128, n0 = blockIdx.x * 128;

    float acc[2][8][4];
#pragma unroll
    for (int mt = 0; mt < 2; mt++)
#pragma unroll
        for (int nt = 0; nt < 8; nt++)
#pragma unroll
            for (int e = 0; e < 4; e++) acc[mt][nt][e] = 0.f;

    int a_r = lane & 15, a_c = (lane >> 4) << 3;
    int b_r = (lane & 7) + ((lane >> 4) << 3), b_c = ((lane >> 3) & 1) << 3;

    auto issue = [&](int s, int kc) {
#pragma unroll
        for (int i = 0; i < 2; i++) {
            int idx = tid + i * 256;
            int r = idx >> 2, c = (idx & 3) << 3;
            uint32_t so = (uint32_t)(r * 40 + c) * 2;
            uint32_t sb = smb + s * KP_STAGE;
            size_t ga = (size_t)(m0 + r) * C_ + kc * 32 + c;
            size_t gb = (size_t)(n0 + r) * C_ + kc * 32 + c;
            cp16(sb + KP_AH + so, ahi_g + ga);
            cp16(sb + KP_AL + so, alo_g + ga);
            cp16(sb + KP_BH + so, bhi_g + gb);
            cp16(sb + KP_BL + so, blo_g + gb);
        }
    };

    issue(0, 0);
    asm volatile("cp.async.commit_group;");

    for (int kc = 0; kc < 32; kc++) {
        int cur = kc & 1;
        if (kc + 1 < 32) {
            issue(cur ^ 1, kc + 1);
            asm volatile("cp.async.commit_group;");
            asm volatile("cp.async.wait_group 1;");
        } else {
            asm volatile("cp.async.wait_group 0;");
        }
        __syncthreads();

        uint32_t base = smb + cur * KP_STAGE;
#pragma unroll
        for (int ks = 0; ks < 2; ks++) {
            int k0 = ks * 16;
            uint32_t Ah[2][4], Al[2][4], Bf[4][4];
#pragma unroll
            for (int mt = 0; mt < 2; mt++) {
                ldsm4(Ah[mt], base + KP_AH + ((wm * 32 + mt * 16 + a_r) * 40 + k0 + a_c) * 2);
                ldsm4(Al[mt], base + KP_AL + ((wm * 32 + mt * 16 + a_r) * 40 + k0 + a_c) * 2);
            }
#pragma unroll
            for (int p = 0; p < 4; p++)
                ldsm4(Bf[p], base + KP_BH + ((wn * 64 + p * 16 + b_r) * 40 + k0 + b_c) * 2);
#pragma unroll
            for (int mt = 0; mt < 2; mt++)
#pragma unroll
                for (int p = 0; p < 4; p++) {
                    mma16816(acc[mt][2 * p],     Ah[mt], Bf[p][0], Bf[p][1]);
                    mma16816(acc[mt][2 * p + 1], Ah[mt], Bf[p][2], Bf[p][3]);
                    mma16816(acc[mt][2 * p],     Al[mt], Bf[p][0], Bf[p][1]);
                    mma16816(acc[mt][2 * p + 1], Al[mt], Bf[p][2], Bf[p][3]);
                }
#pragma unroll
            for (int p = 0; p < 4; p++)
                ldsm4(Bf[p], base + KP_BL + ((wn * 64 + p * 16 + b_r) * 40 + k0 + b_c) * 2);
#pragma unroll
            for (int mt = 0; mt < 2; mt++)
#pragma unroll
                for (int p = 0; p < 4; p++) {
                    mma16816(acc[mt][2 * p],     Ah[mt], Bf[p][0], Bf[p][1]);
                    mma16816(acc[mt][2 * p + 1], Ah[mt], Bf[p][2], Bf[p][3]);
                }
        }
        __syncthreads();
    }

    int gid = lane >> 2, lid2 = (lane & 3) * 2;
#pragma unroll
    for (int mt = 0; mt < 2; mt++)
#pragma unroll
        for (int nt = 0; nt < 8; nt++) {
            int row = m0 + wm * 32 + mt * 16 + gid;
            int col = n0 + wn * 64 + nt * 8 + lid2;
            bf16 h0, h1, h2, h3, l0, l1, l2, l3;
            split_bf16(acc[mt][nt][0], h0, l0);
            split_bf16(acc[mt][nt][1], h1, l1);
            split_bf16(acc[mt][nt][2], h2, l2);
            split_bf16(acc[mt][nt][3], h3, l3);
            *(bf162*)(khi_g + (size_t)row * C_ + col)       = bf162(h0, h1);
            *(bf162*)(klo_g + (size_t)row * C_ + col)       = bf162(l0, l1);
            *(bf162*)(khi_g + (size_t)(row + 8) * C_ + col) = bf162(h2, h3);
            *(bf162*)(klo_g + (size_t)(row + 8) * C_ + col) = bf162(l2, l3);
        }
}

// ---------------- fused attention: QK^T -> exp -> e@V -> outputs ------------
// grid (4, 16, 8), 256 thr; warps: wm=wid>>2 (q 32), wn=wid&3 (k-slice 32)
#define FS_QH 0
#define FS_QL 9216
#define FS_KH 18432
#define FS_KL 36864
#define FS_VH 55296
#define FS_VL 73728
#define FS_MS 92160
#define FS_LS 92672
#define FS_LI 92928
#define FS_SMEM 93184

__global__ __launch_bounds__(256) void attn_fused(
    const bf16* __restrict__ qhi, const bf16* __restrict__ qlo,
    const bf16* __restrict__ khi, const bf16* __restrict__ klo,
    const bf16* __restrict__ vhi, const bf16* __restrict__ vlo,
    const float* __restrict__ bias, const int* __restrict__ mask,
    const float* __restrict__ query,
    float* __restrict__ attn, float* __restrict__ out0)
{
    extern __shared__ char sm[];
    uint32_t smb = smem_u32(sm);
    int b = blockIdx.z, h = blockIdx.y, q0 = blockIdx.x * 64;
    int tid = threadIdx.x, lane = tid & 31, wid = tid >> 5;
    int wm = wid >> 2, wn = wid & 3;
    int* Ms = (int*)(sm + FS_MS);
    float* lsum = (float*)(sm + FS_LS);
    float* Li = (float*)(sm + FS_LI);
    if (tid < 64) lsum[tid] = 0.f;

    // stage Q tile
#pragma unroll
    for (int i = 0; i < 2; i++) {
        int idx = tid + i * 256;
        int r = idx >> 3, c = (idx & 7) << 3;
        size_t g = (size_t)(b * NQ_ + q0 + r) * C_ + h * D_ + c;
        *(uint4*)(sm + FS_QH + (r * 72 + c) * 2) = *(const uint4*)(qhi + g);
        *(uint4*)(sm + FS_QL + (r * 72 + c) * 2) = *(const uint4*)(qlo + g);
    }
    __syncthreads();

    int a_r = lane & 15, a_c = (lane >> 4) << 3;
    int b_r = (lane & 7) + ((lane >> 4) << 3), b_c = ((lane >> 3) & 1) << 3;
    int v_r = (lane & 7) + (((lane >> 3) & 1) << 3), v_c = (lane >> 4) << 3;
    int gid = lane >> 2, lid2 = (lane & 3) * 2;

    uint32_t Qh[2][4][4], Ql[2][4][4];
#pragma unroll
    for (int mt = 0; mt < 2; mt++)
#pragma unroll
        for (int ks = 0; ks < 4; ks++) {
            ldsm4(Qh[mt][ks], smb + FS_QH + ((wm * 32 + mt * 16 + a_r) * 72 + ks * 16 + a_c) * 2);
            ldsm4(Ql[mt][ks], smb + FS_QL + ((wm * 32 + mt * 16 + a_r) * 72 + ks * 16 + a_c) * 2);
        }

    float out[2][8][4];
#pragma unroll
    for (int mt = 0; mt < 2; mt++)
#pragma unroll
        for (int n8 = 0; n8 < 8; n8++)
#pragma unroll
            for (int e = 0; e < 4; e++) out[mt][n8][e] = 0.f;

    float rsum[2][2] = { {0.f, 0.f}, {0.f, 0.f} };

    for (int k0 = 0; k0 < NK_; k0 += 128) {
        __syncthreads();
#pragma unroll
        for (int i = 0; i < 4; i++) {
            int idx = tid + i * 256;
            int r = idx >> 3, c = (idx & 7) << 3;
            size_t g = (size_t)(b * NK_ + k0 + r) * C_ + h * D_ + c;
            *(uint4*)(sm + FS_KH + (r * 72 + c) * 2) = *(const uint4*)(khi + g);
            *(uint4*)(sm + FS_KL + (r * 72 + c) * 2) = *(const uint4*)(klo + g);
            *(uint4*)(sm + FS_VH + (r * 72 + c) * 2) = *(const uint4*)(vhi + g);
            *(uint4*)(sm + FS_VL + (r * 72 + c) * 2) = *(const uint4*)(vlo + g);
        }
        if (tid < 128) Ms[tid] = mask[b * NK_ + k0 + tid];
        __syncthreads();

        // ---- QK^T (3-term split) ----
        float acc[2][4][4];
#pragma unroll
        for (int mt = 0; mt < 2; mt++)
#pragma unroll
            for (int nf = 0; nf < 4; nf++)
#pragma unroll
                for (int e = 0; e < 4; e++) acc[mt][nf][e] = 0.f;

#pragma unroll
        for (int ks = 0; ks < 4; ks++) {
            uint32_t Bh[2][4], Bl[2][4];
#pragma unroll
            for (int np = 0; np < 2; np++) {
                ldsm4(Bh[np], smb + FS_KH + ((wn * 32 + np * 16 + b_r) * 72 + ks * 16 + b_c) * 2);
                ldsm4(Bl[np], smb + FS_KL + ((wn * 32 + np * 16 + b_r) * 72 + ks * 16 + b_c) * 2);
            }
#pragma unroll
            for (int mt = 0; mt < 2; mt++)
#pragma unroll
                for (int np = 0; np < 2; np++) {
                    mma16816(acc[mt][2 * np],     Qh[mt][ks], Bh[np][0], Bh[np][1]);
                    mma16816(acc[mt][2 * np + 1], Qh[mt][ks], Bh[np][2], Bh[np][3]);
                    mma16816(acc[mt][2 * np],     Ql[mt][ks], Bh[np][0], Bh[np][1]);
                    mma16816(acc[mt][2 * np + 1], Ql[mt][ks], Bh[np][2], Bh[np][3]);
                    mma16816(acc[mt][2 * np],     Qh[mt][ks], Bl[np][0], Bl[np][1]);
                    mma16816(acc[mt][2 * np + 1], Qh[mt][ks], Bl[np][2], Bl[np][3]);
                }
        }

        // ---- bias + mask + exp (75% poly / 25% MUFU), write e, build P frags
        uint32_t Pha[2][4], Phb[2][4], Pla[2][4], Plb[2][4];
#pragma unroll
        for (int mt = 0; mt < 2; mt++)
#pragma unroll
            for (int nf = 0; nf < 4; nf++) {
                int cl = wn * 32 + nf * 8 + lid2;
                int col = k0 + cl;
                int msk0 = Ms[cl], msk1 = Ms[cl + 1];
                size_t row0 = ((size_t)((b * H_ + h) * NQ_) + q0 + wm * 32 + mt * 16 + gid) * NK_;
                size_t row1 = row0 + (size_t)8 * NK_;
                float2 bv0 = *(const float2*)(bias + row0 + col);
                float2 bv1 = *(const float2*)(bias + row1 + col);

                float2 r0 = exp_poly2(acc[mt][nf][0], acc[mt][nf][1], bv0.x, bv0.y);
                float e00 = msk0 ? 0.f : r0.x;
                float e01 = msk1 ? 0.f : r0.y;

                float e10, e11;
                if (nf & 1) {   // MUFU quarter
                    e10 = msk0 ? 0.f : __expf(acc[mt][nf][2] * 0.125f + bv1.x);
                    e11 = msk1 ? 0.f : __expf(acc[mt][nf][3] * 0.125f + bv1.y);
                } else {        // poly
                    float2 r1 = exp_poly2(acc[mt][nf][2], acc[mt][nf][3], bv1.x, bv1.y);
                    e10 = msk0 ? 0.f : r1.x;
                    e11 = msk1 ? 0.f : r1.y;
                }

                *(float2*)(attn + row0 + col) = make_float2(e00, e01);
                *(float2*)(attn + row1 + col) = make_float2(e10, e11);
                rsum[mt][0] += e00 + e01;
                rsum[mt][1] += e10 + e11;

                // c-frag -> A-frag repack (hi/lo split, register level)
                bf162 h01 = __floats2bfloat162_rn(e00, e01);
                bf162 l01 = __floats2bfloat162_rn(e00 - __low2float(h01),
                                                  e01 - __high2float(h01));
                bf162 h23 = __floats2bfloat162_rn(e10, e11);
                bf162 l23 = __floats2bfloat162_rn(e10 - __low2float(h23),
                                                  e11 - __high2float(h23));
                Pha[mt][nf] = *(uint32_t*)&h01;
                Pla[mt][nf] = *(uint32_t*)&l01;
                Phb[mt][nf] = *(uint32_t*)&h23;
                Plb[mt][nf] = *(uint32_t*)&l23;
            }

        // ---- P@V over this warp's 32-k slice ----
#pragma unroll
        for (int kt = 0; kt < 2; kt++) {
            uint32_t Ahi[2][4], Alo[2][4];
#pragma unroll
            for (int mt = 0; mt < 2; mt++) {
                Ahi[mt][0] = Pha[mt][2 * kt];     Ahi[mt][1] = Phb[mt][2 * kt];
                Ahi[mt][2] = Pha[mt][2 * kt + 1]; Ahi[mt][3] = Phb[mt][2 * kt + 1];
                Alo[mt][0] = Pla[mt][2 * kt];     Alo[mt][1] = Plb[mt][2 * kt];
                Alo[mt][2] = Pla[mt][2 * kt + 1]; Alo[mt][3] = Plb[mt][2 * kt + 1];
            }
#pragma unroll
            for (int dg = 0; dg < 4; dg++) {
                uint32_t Bh[4], Bl[4];
                ldsm4t(Bh, smb + FS_VH + ((wn * 32 + kt * 16 + v_r) * 72 + dg * 16 + v_c) * 2);
                ldsm4t(Bl, smb + FS_VL + ((wn * 32 + kt * 16 + v_r) * 72 + dg * 16 + v_c) * 2);
#pragma unroll
                for (int mt = 0; mt < 2; mt++)
#pragma unroll
                    for (int nn = 0; nn < 2; nn++) {
                        int n8 = dg * 2 + nn;
                        mma16816(out[mt][n8], Ahi[mt], Bh[nn * 2], Bh[nn * 2 + 1]);
                        mma16816(out[mt][n8], Alo[mt], Bh[nn * 2], Bh[nn * 2 + 1]);
                        mma16816(out[mt][n8], Ahi[mt], Bl[nn * 2], Bl[nn * 2 + 1]);
                    }
            }
        }
    }

    // ---- row sums -> smem ----
#pragma unroll
    for (int mt = 0; mt < 2; mt++)
#pragma unroll
        for (int rr = 0; rr < 2; rr++) {
            float v = rsum[mt][rr];
            v += __shfl_xor_sync(0xffffffffu, v, 1);
            v += __shfl_xor_sync(0xffffffffu, v, 2);
            if ((lane & 3) == 0)
                atomicAdd(&lsum[wm * 32 + mt * 16 + gid + rr * 8], v);
        }

    // RACE FIX: all warps must finish reading V (ldsm4t above) before obuf
    // overwrites the staging region (obuf spans 64KB, overlapping FS_VH).
    __syncthreads();

    // ---- out partials -> smem (reuse staging region) ----
    float* obuf = (float*)sm;
#pragma unroll
    for (int mt = 0; mt < 2; mt++)
#pragma unroll
        for (int n8 = 0; n8 < 8; n8++) {
            int r0 = ((wm * 4 + wn) * 32 + mt * 16 + gid) * 64 + n8 * 8 + lid2;
            obuf[r0]     = out[mt][n8][0];
            obuf[r0 + 1] = out[mt][n8][1];
            int r1 = r0 + 8 * 64;
            obuf[r1]     = out[mt][n8][2];
            obuf[r1 + 1] = out[mt][n8][3];
        }
    __syncthreads();
    if (tid < 64) Li[tid] = 1.0f / lsum[tid];
    __syncthreads();

    // ---- reduce over wn, residual, write out0 ----
    if (out0) {
        for (int i = tid; i < 4096; i += 256) {
            int qr = i >> 6, d = i & 63;
            int wmq = qr >> 5, qq = qr & 31;
            float s = obuf[((wmq * 4 + 0) * 32 + qq) * 64 + d]
                    + obuf[((wmq * 4 + 1) * 32 + qq) * 64 + d]
                    + obuf[((wmq * 4 + 2) * 32 + qq) * 64 + d]
                    + obuf[((wmq * 4 + 3) * 32 + qq) * 64 + d];
            size_t o = (size_t)(b * NQ_ + q0 + qr) * C_ + h * D_ + d;
            out0[o] = query[o] + s * Li[qr];
        }
    }

    // ---- rescale own e tile: p = e / l (mostly L2-resident) ----
    {
        size_t base = ((size_t)((b * H_ + h) * NQ_) + q0) * NK_;
        for (int j = 0; j < 256; j++) {
            int idx = j * 256 + tid;
            int row = idx >> 10;
            int c4 = (idx & 1023) * 4;
            size_t a = base + (size_t)row * NK_ + c4;
            float4 e = *(const float4*)(attn + a);
            float li = Li[row];
            e.x *= li; e.y *= li; e.z *= li; e.w *= li;
            *(float4*)(attn + a) = e;
        }
    }
}

// ---------------- host ------------------------------------------------------
extern "C" void kernel_launch(void* const* d_in, const int* in_sizes, int n_in,
                              void* d_out, int out_size)
{
    const float* query  = (const float*)d_in[0];
    const float* memory = (const float*)d_in[1];
    const float* qpos   = (const float*)d_in[2];
    const float* mpos   = (const float*)d_in[3];
    const float* bias   = (const float*)d_in[4];
    const int*   mask   = (const int*)d_in[5];
    const float* Wk     = (const float*)d_in[6];
    const float* lnqw   = (const float*)d_in[7];
    const float* lnqb   = (const float*)d_in[8];
    const float* lnkw   = (const float*)d_in[9];
    const float* lnkb   = (const float*)d_in[10];
    (void)in_sizes; (void)n_in;

    float* out = (float*)d_out;
    const long long OUT0 = (long long)B_ * NQ_ * C_;
    const long long ATT  = (long long)B_ * H_ * NQ_ * NK_;

    float* out0 = nullptr;
    float* attn = nullptr;
    if ((long long)out_size >= OUT0 + ATT) { out0 = out; attn = out + OUT0; }
    else if ((long long)out_size >= ATT)   { attn = out; }
    else {
        out0 = out;
        cudaGetSymbolAddress((void**)&attn, g_scores);
    }

    bf16 *qhi, *qlo, *ahi, *alo, *vhi, *vlo, *khi, *klo, *bhi, *blo;
    cudaGetSymbolAddress((void**)&qhi, g_qhi);
    cudaGetSymbolAddress((void**)&qlo, g_qlo);
    cudaGetSymbolAddress((void**)&ahi, g_ahi);
    cudaGetSymbolAddress((void**)&alo, g_alo);
    cudaGetSymbolAddress((void**)&vhi, g_vhi);
    cudaGetSymbolAddress((void**)&vlo, g_vlo);
    cudaGetSymbolAddress((void**)&khi, g_khi);
    cudaGetSymbolAddress((void**)&klo, g_klo);
    cudaGetSymbolAddress((void**)&bhi, g_bhi);
    cudaGetSymbolAddress((void**)&blo, g_blo);

    cudaFuncSetAttribute(kproj_mma,  cudaFuncAttributeMaxDynamicSharedMemorySize, KP_SMEM);
    cudaFuncSetAttribute(attn_fused, cudaFuncAttributeMaxDynamicSharedMemorySize, FS_SMEM);

    ln_q_kernel<<<B_ * NQ_, 256>>>(query, lnqw, lnqb, qpos, qhi, qlo);
    ln_k_kernel<<<B_ * NK_, 256>>>(memory, lnkw, lnkb, mpos, vhi, vlo, ahi, alo);
    wconv_kernel<<<C_ * C_ / 1024, 256>>>(Wk, bhi, blo);
    {
        dim3 grid(C_ / 128, (B_ * NK_) / 128);
        kproj_mma<<<grid, 256, KP_SMEM>>>(ahi, alo, bhi, blo, khi, klo);
    }
    {
        dim3 grid(NQ_ / 64, H_, B_);
        attn_fused<<<grid, 256, FS_SMEM>>>(qhi, qlo, khi, klo, vhi, vlo,
                                           bias, mask, query, attn, out0);
    }
}

// round 11
// speedup vs baseline: 1.0023x; 1.0023x over previous
#include <cuda_runtime.h>
#include <cuda_bf16.h>
#include <cstdint>

typedef __nv_bfloat16  bf16;
typedef __nv_bfloat162 bf162;
typedef unsigned long long ull;

#define B_  8
#define NQ_ 256
#define NK_ 4096
#define C_  1024
#define H_  16
#define D_  64

// ---------------- scratch (static device globals) ---------------------------
__device__ bf16 g_qhi[(size_t)B_ * NQ_ * C_];
__device__ bf16 g_qlo[(size_t)B_ * NQ_ * C_];
__device__ bf16 g_ahi[(size_t)B_ * NK_ * C_];
__device__ bf16 g_alo[(size_t)B_ * NK_ * C_];
__device__ bf16 g_vhi[(size_t)B_ * NK_ * C_];
__device__ bf16 g_vlo[(size_t)B_ * NK_ * C_];
__device__ bf16 g_khi[(size_t)B_ * NK_ * C_];
__device__ bf16 g_klo[(size_t)B_ * NK_ * C_];
__device__ bf16 g_bhi[C_ * C_];
__device__ bf16 g_blo[C_ * C_];
__device__ float g_scores[(size_t)B_ * H_ * NQ_ * NK_];

// ---------------- helpers ----------------------------------------------------
__device__ __forceinline__ uint32_t smem_u32(const void* p) {
    uint32_t a;
    asm("{ .reg .u64 t; cvta.to.shared.u64 t, %1; cvt.u32.u64 %0, t; }"
        : "=r"(a) : "l"(p));
    return a;
}
__device__ __forceinline__ void ldsm4(uint32_t* r, uint32_t addr) {
    asm volatile("ldmatrix.sync.aligned.m8n8.x4.shared.b16 {%0,%1,%2,%3}, [%4];"
                 : "=r"(r[0]), "=r"(r[1]), "=r"(r[2]), "=r"(r[3]) : "r"(addr));
}
__device__ __forceinline__ void ldsm4t(uint32_t* r, uint32_t addr) {
    asm volatile("ldmatrix.sync.aligned.m8n8.x4.trans.shared.b16 {%0,%1,%2,%3}, [%4];"
                 : "=r"(r[0]), "=r"(r[1]), "=r"(r[2]), "=r"(r[3]) : "r"(addr));
}
__device__ __forceinline__ void mma16816(float* d, const uint32_t* a,
                                         uint32_t b0, uint32_t b1) {
    asm volatile(
        "mma.sync.aligned.m16n8k16.row.col.f32.bf16.bf16.f32 "
        "{%0,%1,%2,%3}, {%4,%5,%6,%7}, {%8,%9}, {%0,%1,%2,%3};"
        : "+f"(d[0]), "+f"(d[1]), "+f"(d[2]), "+f"(d[3])
        : "r"(a[0]), "r"(a[1]), "r"(a[2]), "r"(a[3]), "r"(b0), "r"(b1));
}
__device__ __forceinline__ void cp16(uint32_t s, const void* g) {
    asm volatile("cp.async.cg.shared.global [%0], [%1], 16;"
                 :: "r"(s), "l"(__cvta_generic_to_global(g)));
}
__device__ __forceinline__ void split_bf16(float x, bf16& h, bf16& l) {
    h = __float2bfloat16(x);
    l = __float2bfloat16(x - __bfloat162float(h));
}
__device__ __forceinline__ ull pack2(float x, float y) {
    ull r;
    asm("mov.b64 %0, {%1, %2};" : "=l"(r)
        : "r"(__float_as_uint(x)), "r"(__float_as_uint(y)));
    return r;
}
__device__ __forceinline__ float2 unpack2(ull v) {
    unsigned lo, hi;
    asm("mov.b64 {%0, %1}, %2;" : "=r"(lo), "=r"(hi) : "l"(v));
    return make_float2(__uint_as_float(lo), __uint_as_float(hi));
}
__device__ __forceinline__ ull fma2(ull a, ull b, ull c) {
    ull d;
    asm("fma.rn.f32x2 %0, %1, %2, %3;" : "=l"(d) : "l"(a), "l"(b), "l"(c));
    return d;
}
__device__ __forceinline__ ull add2(ull a, ull b) {
    ull d;
    asm("add.rn.f32x2 %0, %1, %2;" : "=l"(d) : "l"(a), "l"(b));
    return d;
}

// packed exp(0.125*s + b) on the FMA pipe via exp2 polynomial
__device__ __forceinline__ float2 exp_poly2(float s0, float s1, float b0, float b1) {
    const ull SCL2  = pack2(0.1803368801f, 0.1803368801f);   // 0.125*log2(e)
    const ull L2E2  = pack2(1.44269504f, 1.44269504f);
    const ull CBIG2 = pack2(12582912.f, 12582912.f);          // 1.5*2^23
    const ull CNEG2 = pack2(-12582912.f, -12582912.f);
    const ull NONE2 = pack2(-1.f, -1.f);
    const ull ONE2  = pack2(1.f, 1.f);
    const ull C4P   = pack2(0.0096181291f, 0.0096181291f);
    const ull C3P   = pack2(0.0555041087f, 0.0555041087f);
    const ull C2P   = pack2(0.2402265069f, 0.2402265069f);
    const ull C1P   = pack2(0.6931471806f, 0.6931471806f);
    ull t2 = fma2(pack2(s0, s1), SCL2, fma2(pack2(b0, b1), L2E2, 0ULL));
    ull m2 = add2(t2, CBIG2);
    ull n2 = add2(m2, CNEG2);
    ull f2 = fma2(n2, NONE2, t2);
    ull p2 = fma2(f2, C4P, C3P);
    p2 = fma2(f2, p2, C2P);
    p2 = fma2(f2, p2, C1P);
    p2 = fma2(f2, p2, ONE2);
    float2 mf = unpack2(m2);
    float2 pf = unpack2(p2);
    float e0 = __int_as_float(__float_as_int(pf.x) + (__float_as_int(mf.x) << 23));
    float e1 = __int_as_float(__float_as_int(pf.y) + (__float_as_int(mf.y) << 23));
    return make_float2(e0, e1);
}

// ---------------- LayerNorm core ---------------------------------------------
__device__ __forceinline__ float4 ln_row(const float* x, const float* w,
                                         const float* bw, size_t base, int t,
                                         float* rs, float* rs2) {
    float4 v = *(const float4*)(x + base + t * 4);
    float s  = v.x + v.y + v.z + v.w;
    float s2 = v.x * v.x + v.y * v.y + v.z * v.z + v.w * v.w;
    int lane = t & 31, wid = t >> 5;
#pragma unroll
    for (int o = 16; o > 0; o >>= 1) {
        s  += __shfl_xor_sync(0xffffffffu, s,  o);
        s2 += __shfl_xor_sync(0xffffffffu, s2, o);
    }
    if (lane == 0) { rs[wid] = s; rs2[wid] = s2; }
    __syncthreads();
    if (t == 0) {
        float a = 0.f, b = 0.f;
#pragma unroll
        for (int i = 0; i < 8; i++) { a += rs[i]; b += rs2[i]; }
        rs[0] = a; rs2[0] = b;
    }
    __syncthreads();
    float mu  = rs[0]  * (1.0f / C_);
    float var = rs2[0] * (1.0f / C_) - mu * mu;
    float inv = rsqrtf(var + 1e-5f);
    float4 wv = *(const float4*)(w  + t * 4);
    float4 bv = *(const float4*)(bw + t * 4);
    float4 o;
    o.x = (v.x - mu) * inv * wv.x + bv.x;
    o.y = (v.y - mu) * inv * wv.y + bv.y;
    o.z = (v.z - mu) * inv * wv.z + bv.z;
    o.w = (v.w - mu) * inv * wv.w + bv.w;
    return o;
}

__global__ __launch_bounds__(256) void ln_q_kernel(
    const float* __restrict__ x, const float* __restrict__ w,
    const float* __restrict__ bw, const float* __restrict__ pos,
    bf16* __restrict__ qhi, bf16* __restrict__ qlo)
{
    __shared__ float rs[8], rs2[8];
    int row = blockIdx.x, t = threadIdx.x;
    size_t base = (size_t)row * C_;
    float4 o = ln_row(x, w, bw, base, t, rs, rs2);
    float4 p = *(const float4*)(pos + base + t * 4);
    float a0 = o.x + p.x, a1 = o.y + p.y, a2 = o.z + p.z, a3 = o.w + p.w;
    bf16 h0, h1, h2, h3, l0, l1, l2, l3;
    split_bf16(a0, h0, l0); split_bf16(a1, h1, l1);
    split_bf16(a2, h2, l2); split_bf16(a3, h3, l3);
    *(bf162*)(qhi + base + t * 4)     = bf162(h0, h1);
    *(bf162*)(qhi + base + t * 4 + 2) = bf162(h2, h3);
    *(bf162*)(qlo + base + t * 4)     = bf162(l0, l1);
    *(bf162*)(qlo + base + t * 4 + 2) = bf162(l2, l3);
}

__global__ __launch_bounds__(256) void ln_k_kernel(
    const float* __restrict__ x, const float* __restrict__ w,
    const float* __restrict__ bw, const float* __restrict__ pos,
    bf16* __restrict__ vhi, bf16* __restrict__ vlo,
    bf16* __restrict__ ahi, bf16* __restrict__ alo)
{
    __shared__ float rs[8], rs2[8];
    int row = blockIdx.x, t = threadIdx.x;
    size_t base = (size_t)row * C_;
    float4 o = ln_row(x, w, bw, base, t, rs, rs2);

    bf16 h0, h1, h2, h3, l0, l1, l2, l3;
    split_bf16(o.x, h0, l0); split_bf16(o.y, h1, l1);
    split_bf16(o.z, h2, l2); split_bf16(o.w, h3, l3);
    *(bf162*)(vhi + base + t * 4)     = bf162(h0, h1);
    *(bf162*)(vhi + base + t * 4 + 2) = bf162(h2, h3);
    *(bf162*)(vlo + base + t * 4)     = bf162(l0, l1);
    *(bf162*)(vlo + base + t * 4 + 2) = bf162(l2, l3);

    float4 p = *(const float4*)(pos + base + t * 4);
    float a0 = o.x + p.x, a1 = o.y + p.y, a2 = o.z + p.z, a3 = o.w + p.w;
    split_bf16(a0, h0, l0); split_bf16(a1, h1, l1);
    split_bf16(a2, h2, l2); split_bf16(a3, h3, l3);
    *(bf162*)(ahi + base + t * 4)     = bf162(h0, h1);
    *(bf162*)(ahi + base + t * 4 + 2) = bf162(h2, h3);
    *(bf162*)(alo + base + t * 4)     = bf162(l0, l1);
    *(bf162*)(alo + base + t * 4 + 2) = bf162(l2, l3);
}

__global__ __launch_bounds__(256) void wconv_kernel(
    const float* __restrict__ Wk, bf16* __restrict__ hi, bf16* __restrict__ lo)
{
    size_t i = (size_t)blockIdx.x * 1024 + threadIdx.x * 4;
    float4 v = *(const float4*)(Wk + i);
    bf16 h0, h1, h2, h3, l0, l1, l2, l3;
    split_bf16(v.x, h0, l0); split_bf16(v.y, h1, l1);
    split_bf16(v.z, h2, l2); split_bf16(v.w, h3, l3);
    *(bf162*)(hi + i)     = bf162(h0, h1);
    *(bf162*)(hi + i + 2) = bf162(h2, h3);
    *(bf162*)(lo + i)     = bf162(l0, l1);
    *(bf162*)(lo + i + 2) = bf162(l2, l3);
}

// ---------------- K projection: mma.sync, cp.async 2-stage, 2 CTA/SM --------
#define KP_AH 0
#define KP_AL 10240
#define KP_BH 20480
#define KP_BL 30720
#define KP_STAGE 40960
#define KP_SMEM (2 * KP_STAGE)

__global__ __launch_bounds__(256, 2) void kproj_mma(
    const bf16* __restrict__ ahi_g, const bf16* __restrict__ alo_g,
    const bf16* __restrict__ bhi_g, const bf16* __restrict__ blo_g,
    bf16* __restrict__ khi_g, bf16* __restrict__ klo_g)
{
    extern __shared__ char sm[];
    uint32_t smb = smem_u32(sm);
    int tid = threadIdx.x, lane = tid & 31, wid = tid >> 5;
    int wm = wid >> 1, wn = wid & 1;
    int m0 = blockIdx.y * 128, n0 = blockIdx.x * 128;

    float acc[2][8][4];
#pragma unroll
    for (int mt = 0; mt < 2; mt++)
#pragma unroll
        for (int nt = 0; nt < 8; nt++)
#pragma unroll
            for (int e = 0; e < 4; e++) acc[mt][nt][e] = 0.f;

    int a_r = lane & 15, a_c = (lane >> 4) << 3;
    int b_r = (lane & 7) + ((lane >> 4) << 3), b_c = ((lane >> 3) & 1) << 3;

    auto issue = [&](int s, int kc) {
#pragma unroll
        for (int i = 0; i < 2; i++) {
            int idx = tid + i * 256;
            int r = idx >> 2, c = (idx & 3) << 3;
            uint32_t so = (uint32_t)(r * 40 + c) * 2;
            uint32_t sb = smb + s * KP_STAGE;
            size_t ga = (size_t)(m0 + r) * C_ + kc * 32 + c;
            size_t gb = (size_t)(n0 + r) * C_ + kc * 32 + c;
            cp16(sb + KP_AH + so, ahi_g + ga);
            cp16(sb + KP_AL + so, alo_g + ga);
            cp16(sb + KP_BH + so, bhi_g + gb);
            cp16(sb + KP_BL + so, blo_g + gb);
        }
    };

    issue(0, 0);
    asm volatile("cp.async.commit_group;");

    for (int kc = 0; kc < 32; kc++) {
        int cur = kc & 1;
        if (kc + 1 < 32) {
            issue(cur ^ 1, kc + 1);
            asm volatile("cp.async.commit_group;");
            asm volatile("cp.async.wait_group 1;");
        } else {
            asm volatile("cp.async.wait_group 0;");
        }
        __syncthreads();

        uint32_t base = smb + cur * KP_STAGE;
#pragma unroll
        for (int ks = 0; ks < 2; ks++) {
            int k0 = ks * 16;
            uint32_t Ah[2][4], Al[2][4], Bf[4][4];
#pragma unroll
            for (int mt = 0; mt < 2; mt++) {
                ldsm4(Ah[mt], base + KP_AH + ((wm * 32 + mt * 16 + a_r) * 40 + k0 + a_c) * 2);
                ldsm4(Al[mt], base + KP_AL + ((wm * 32 + mt * 16 + a_r) * 40 + k0 + a_c) * 2);
            }
#pragma unroll
            for (int p = 0; p < 4; p++)
                ldsm4(Bf[p], base + KP_BH + ((wn * 64 + p * 16 + b_r) * 40 + k0 + b_c) * 2);
#pragma unroll
            for (int mt = 0; mt < 2; mt++)
#pragma unroll
                for (int p = 0; p < 4; p++) {
                    mma16816(acc[mt][2 * p],     Ah[mt], Bf[p][0], Bf[p][1]);
                    mma16816(acc[mt][2 * p + 1], Ah[mt], Bf[p][2], Bf[p][3]);
                    mma16816(acc[mt][2 * p],     Al[mt], Bf[p][0], Bf[p][1]);
                    mma16816(acc[mt][2 * p + 1], Al[mt], Bf[p][2], Bf[p][3]);
                }
#pragma unroll
            for (int p = 0; p < 4; p++)
                ldsm4(Bf[p], base + KP_BL + ((wn * 64 + p * 16 + b_r) * 40 + k0 + b_c) * 2);
#pragma unroll
            for (int mt = 0; mt < 2; mt++)
#pragma unroll
                for (int p = 0; p < 4; p++) {
                    mma16816(acc[mt][2 * p],     Ah[mt], Bf[p][0], Bf[p][1]);
                    mma16816(acc[mt][2 * p + 1], Ah[mt], Bf[p][2], Bf[p][3]);
                }
        }
        __syncthreads();
    }

    int gid = lane >> 2, lid2 = (lane & 3) * 2;
#pragma unroll
    for (int mt = 0; mt < 2; mt++)
#pragma unroll
        for (int nt = 0; nt < 8; nt++) {
            int row = m0 + wm * 32 + mt * 16 + gid;
            int col = n0 + wn * 64 + nt * 8 + lid2;
            bf16 h0, h1, h2, h3, l0, l1, l2, l3;
            split_bf16(acc[mt][nt][0], h0, l0);
            split_bf16(acc[mt][nt][1], h1, l1);
            split_bf16(acc[mt][nt][2], h2, l2);
            split_bf16(acc[mt][nt][3], h3, l3);
            *(bf162*)(khi_g + (size_t)row * C_ + col)       = bf162(h0, h1);
            *(bf162*)(klo_g + (size_t)row * C_ + col)       = bf162(l0, l1);
            *(bf162*)(khi_g + (size_t)(row + 8) * C_ + col) = bf162(h2, h3);
            *(bf162*)(klo_g + (size_t)(row + 8) * C_ + col) = bf162(l2, l3);
        }
}

// ---------------- fused attention: QK^T -> exp -> e@V -> outputs ------------
// grid (4, 16, 8), 256 thr; warps: wm=wid>>2 (q 32), wn=wid&3 (k-slice 32)
#define FS_QH 0
#define FS_QL 9216
#define FS_KH 18432
#define FS_KL 36864
#define FS_VH 55296
#define FS_VL 73728
#define FS_MS 92160
#define FS_LS 92672
#define FS_LI 92928
#define FS_SMEM 93184

__global__ __launch_bounds__(256) void attn_fused(
    const bf16* __restrict__ qhi, const bf16* __restrict__ qlo,
    const bf16* __restrict__ khi, const bf16* __restrict__ klo,
    const bf16* __restrict__ vhi, const bf16* __restrict__ vlo,
    const float* __restrict__ bias, const int* __restrict__ mask,
    const float* __restrict__ query,
    float* __restrict__ attn, float* __restrict__ out0)
{
    extern __shared__ char sm[];
    uint32_t smb = smem_u32(sm);
    int b = blockIdx.z, h = blockIdx.y, q0 = blockIdx.x * 64;
    int tid = threadIdx.x, lane = tid & 31, wid = tid >> 5;
    int wm = wid >> 2, wn = wid & 3;
    int* Ms = (int*)(sm + FS_MS);
    float* lsum = (float*)(sm + FS_LS);
    float* Li = (float*)(sm + FS_LI);
    if (tid < 64) lsum[tid] = 0.f;

    // stage Q tile
#pragma unroll
    for (int i = 0; i < 2; i++) {
        int idx = tid + i * 256;
        int r = idx >> 3, c = (idx & 7) << 3;
        size_t g = (size_t)(b * NQ_ + q0 + r) * C_ + h * D_ + c;
        *(uint4*)(sm + FS_QH + (r * 72 + c) * 2) = *(const uint4*)(qhi + g);
        *(uint4*)(sm + FS_QL + (r * 72 + c) * 2) = *(const uint4*)(qlo + g);
    }
    __syncthreads();

    int a_r = lane & 15, a_c = (lane >> 4) << 3;
    int b_r = (lane & 7) + ((lane >> 4) << 3), b_c = ((lane >> 3) & 1) << 3;
    int v_r = (lane & 7) + (((lane >> 3) & 1) << 3), v_c = (lane >> 4) << 3;
    int gid = lane >> 2, lid2 = (lane & 3) * 2;

    uint32_t Qh[2][4][4], Ql[2][4][4];
#pragma unroll
    for (int mt = 0; mt < 2; mt++)
#pragma unroll
        for (int ks = 0; ks < 4; ks++) {
            ldsm4(Qh[mt][ks], smb + FS_QH + ((wm * 32 + mt * 16 + a_r) * 72 + ks * 16 + a_c) * 2);
            ldsm4(Ql[mt][ks], smb + FS_QL + ((wm * 32 + mt * 16 + a_r) * 72 + ks * 16 + a_c) * 2);
        }

    float out[2][8][4];
#pragma unroll
    for (int mt = 0; mt < 2; mt++)
#pragma unroll
        for (int n8 = 0; n8 < 8; n8++)
#pragma unroll
            for (int e = 0; e < 4; e++) out[mt][n8][e] = 0.f;

    float rsum[2][2] = { {0.f, 0.f}, {0.f, 0.f} };

    for (int k0 = 0; k0 < NK_; k0 += 128) {
        __syncthreads();
#pragma unroll
        for (int i = 0; i < 4; i++) {
            int idx = tid + i * 256;
            int r = idx >> 3, c = (idx & 7) << 3;
            size_t g = (size_t)(b * NK_ + k0 + r) * C_ + h * D_ + c;
            *(uint4*)(sm + FS_KH + (r * 72 + c) * 2) = *(const uint4*)(khi + g);
            *(uint4*)(sm + FS_KL + (r * 72 + c) * 2) = *(const uint4*)(klo + g);
            *(uint4*)(sm + FS_VH + (r * 72 + c) * 2) = *(const uint4*)(vhi + g);
            *(uint4*)(sm + FS_VL + (r * 72 + c) * 2) = *(const uint4*)(vlo + g);
        }
        if (tid < 128) Ms[tid] = mask[b * NK_ + k0 + tid];
        __syncthreads();

        // ---- QK^T (3-term split) ----
        float acc[2][4][4];
#pragma unroll
        for (int mt = 0; mt < 2; mt++)
#pragma unroll
            for (int nf = 0; nf < 4; nf++)
#pragma unroll
                for (int e = 0; e < 4; e++) acc[mt][nf][e] = 0.f;

#pragma unroll
        for (int ks = 0; ks < 4; ks++) {
            uint32_t Bh[2][4], Bl[2][4];
#pragma unroll
            for (int np = 0; np < 2; np++) {
                ldsm4(Bh[np], smb + FS_KH + ((wn * 32 + np * 16 + b_r) * 72 + ks * 16 + b_c) * 2);
                ldsm4(Bl[np], smb + FS_KL + ((wn * 32 + np * 16 + b_r) * 72 + ks * 16 + b_c) * 2);
            }
#pragma unroll
            for (int mt = 0; mt < 2; mt++)
#pragma unroll
                for (int np = 0; np < 2; np++) {
                    mma16816(acc[mt][2 * np],     Qh[mt][ks], Bh[np][0], Bh[np][1]);
                    mma16816(acc[mt][2 * np + 1], Qh[mt][ks], Bh[np][2], Bh[np][3]);
                    mma16816(acc[mt][2 * np],     Ql[mt][ks], Bh[np][0], Bh[np][1]);
                    mma16816(acc[mt][2 * np + 1], Ql[mt][ks], Bh[np][2], Bh[np][3]);
                    mma16816(acc[mt][2 * np],     Qh[mt][ks], Bl[np][0], Bl[np][1]);
                    mma16816(acc[mt][2 * np + 1], Qh[mt][ks], Bl[np][2], Bl[np][3]);
                }
        }

        // ---- bias + mask + exp (75% poly / 25% MUFU), write e, build P frags
        uint32_t Pha[2][4], Phb[2][4], Pla[2][4], Plb[2][4];
#pragma unroll
        for (int mt = 0; mt < 2; mt++)
#pragma unroll
            for (int nf = 0; nf < 4; nf++) {
                int cl = wn * 32 + nf * 8 + lid2;
                int col = k0 + cl;
                int msk0 = Ms[cl], msk1 = Ms[cl + 1];
                size_t row0 = ((size_t)((b * H_ + h) * NQ_) + q0 + wm * 32 + mt * 16 + gid) * NK_;
                size_t row1 = row0 + (size_t)8 * NK_;
                float2 bv0 = *(const float2*)(bias + row0 + col);
                float2 bv1 = *(const float2*)(bias + row1 + col);

                float2 r0 = exp_poly2(acc[mt][nf][0], acc[mt][nf][1], bv0.x, bv0.y);
                float e00 = msk0 ? 0.f : r0.x;
                float e01 = msk1 ? 0.f : r0.y;

                float e10, e11;
                if (nf & 1) {   // MUFU quarter
                    e10 = msk0 ? 0.f : __expf(acc[mt][nf][2] * 0.125f + bv1.x);
                    e11 = msk1 ? 0.f : __expf(acc[mt][nf][3] * 0.125f + bv1.y);
                } else {        // poly
                    float2 r1 = exp_poly2(acc[mt][nf][2], acc[mt][nf][3], bv1.x, bv1.y);
                    e10 = msk0 ? 0.f : r1.x;
                    e11 = msk1 ? 0.f : r1.y;
                }

                *(float2*)(attn + row0 + col) = make_float2(e00, e01);
                *(float2*)(attn + row1 + col) = make_float2(e10, e11);
                rsum[mt][0] += e00 + e01;
                rsum[mt][1] += e10 + e11;

                // c-frag -> A-frag repack (hi/lo split, register level)
                bf162 h01 = __floats2bfloat162_rn(e00, e01);
                bf162 l01 = __floats2bfloat162_rn(e00 - __low2float(h01),
                                                  e01 - __high2float(h01));
                bf162 h23 = __floats2bfloat162_rn(e10, e11);
                bf162 l23 = __floats2bfloat162_rn(e10 - __low2float(h23),
                                                  e11 - __high2float(h23));
                Pha[mt][nf] = *(uint32_t*)&h01;
                Pla[mt][nf] = *(uint32_t*)&l01;
                Phb[mt][nf] = *(uint32_t*)&h23;
                Plb[mt][nf] = *(uint32_t*)&l23;
            }

        // ---- P@V over this warp's 32-k slice ----
#pragma unroll
        for (int kt = 0; kt < 2; kt++) {
            uint32_t Ahi[2][4], Alo[2][4];
#pragma unroll
            for (int mt = 0; mt < 2; mt++) {
                Ahi[mt][0] = Pha[mt][2 * kt];     Ahi[mt][1] = Phb[mt][2 * kt];
                Ahi[mt][2] = Pha[mt][2 * kt + 1]; Ahi[mt][3] = Phb[mt][2 * kt + 1];
                Alo[mt][0] = Pla[mt][2 * kt];     Alo[mt][1] = Plb[mt][2 * kt];
                Alo[mt][2] = Pla[mt][2 * kt + 1]; Alo[mt][3] = Plb[mt][2 * kt + 1];
            }
#pragma unroll
            for (int dg = 0; dg < 4; dg++) {
                uint32_t Bh[4], Bl[4];
                ldsm4t(Bh, smb + FS_VH + ((wn * 32 + kt * 16 + v_r) * 72 + dg * 16 + v_c) * 2);
                ldsm4t(Bl, smb + FS_VL + ((wn * 32 + kt * 16 + v_r) * 72 + dg * 16 + v_c) * 2);
#pragma unroll
                for (int mt = 0; mt < 2; mt++)
#pragma unroll
                    for (int nn = 0; nn < 2; nn++) {
                        int n8 = dg * 2 + nn;
                        mma16816(out[mt][n8], Ahi[mt], Bh[nn * 2], Bh[nn * 2 + 1]);
                        mma16816(out[mt][n8], Alo[mt], Bh[nn * 2], Bh[nn * 2 + 1]);
                        mma16816(out[mt][n8], Ahi[mt], Bl[nn * 2], Bl[nn * 2 + 1]);
                    }
            }
        }
    }

    // ---- row sums -> smem ----
#pragma unroll
    for (int mt = 0; mt < 2; mt++)
#pragma unroll
        for (int rr = 0; rr < 2; rr++) {
            float v = rsum[mt][rr];
            v += __shfl_xor_sync(0xffffffffu, v, 1);
            v += __shfl_xor_sync(0xffffffffu, v, 2);
            if ((lane & 3) == 0)
                atomicAdd(&lsum[wm * 32 + mt * 16 + gid + rr * 8], v);
        }

    // RACE FIX: all warps must finish reading V (ldsm4t above) before obuf
    // overwrites the staging region (obuf spans 64KB, overlapping FS_VH).
    __syncthreads();

    // ---- out partials -> smem (reuse staging region) ----
    float* obuf = (float*)sm;
#pragma unroll
    for (int mt = 0; mt < 2; mt++)
#pragma unroll
        for (int n8 = 0; n8 < 8; n8++) {
            int r0 = ((wm * 4 + wn) * 32 + mt * 16 + gid) * 64 + n8 * 8 + lid2;
            obuf[r0]     = out[mt][n8][0];
            obuf[r0 + 1] = out[mt][n8][1];
            int r1 = r0 + 8 * 64;
            obuf[r1]     = out[mt][n8][2];
            obuf[r1 + 1] = out[mt][n8][3];
        }
    __syncthreads();
    if (tid < 64) Li[tid] = 1.0f / lsum[tid];
    __syncthreads();

    // ---- reduce over wn, residual, write out0 ----
    if (out0) {
        for (int i = tid; i < 4096; i += 256) {
            int qr = i >> 6, d = i & 63;
            int wmq = qr >> 5, qq = qr & 31;
            float s = obuf[((wmq * 4 + 0) * 32 + qq) * 64 + d]
                    + obuf[((wmq * 4 + 1) * 32 + qq) * 64 + d]
                    + obuf[((wmq * 4 + 2) * 32 + qq) * 64 + d]
                    + obuf[((wmq * 4 + 3) * 32 + qq) * 64 + d];
            size_t o = (size_t)(b * NQ_ + q0 + qr) * C_ + h * D_ + d;
            out0[o] = query[o] + s * Li[qr];
        }
    }

    // ---- rescale own e tile: p = e / l (mostly L2-resident) ----
    {
        size_t base = ((size_t)((b * H_ + h) * NQ_) + q0) * NK_;
        for (int j = 0; j < 256; j++) {
            int idx = j * 256 + tid;
            int row = idx >> 10;
            int c4 = (idx & 1023) * 4;
            size_t a = base + (size_t)row * NK_ + c4;
            float4 e = *(const float4*)(attn + a);
            float li = Li[row];
            e.x *= li; e.y *= li; e.z *= li; e.w *= li;
            *(float4*)(attn + a) = e;
        }
    }
}

// ---------------- host ------------------------------------------------------
extern "C" void kernel_launch(void* const* d_in, const int* in_sizes, int n_in,
                              void* d_out, int out_size)
{
    const float* query  = (const float*)d_in[0];
    const float* memory = (const float*)d_in[1];
    const float* qpos   = (const float*)d_in[2];
    const float* mpos   = (const float*)d_in[3];
    const float* bias   = (const float*)d_in[4];
    const int*   mask   = (const int*)d_in[5];
    const float* Wk     = (const float*)d_in[6];
    const float* lnqw   = (const float*)d_in[7];
    const float* lnqb   = (const float*)d_in[8];
    const float* lnkw   = (const float*)d_in[9];
    const float* lnkb   = (const float*)d_in[10];
    (void)in_sizes; (void)n_in;

    float* out = (float*)d_out;
    const long long OUT0 = (long long)B_ * NQ_ * C_;
    const long long ATT  = (long long)B_ * H_ * NQ_ * NK_;

    float* out0 = nullptr;
    float* attn = nullptr;
    if ((long long)out_size >= OUT0 + ATT) { out0 = out; attn = out + OUT0; }
    else if ((long long)out_size >= ATT)   { attn = out; }
    else {
        out0 = out;
        cudaGetSymbolAddress((void**)&attn, g_scores);
    }

    bf16 *qhi, *qlo, *ahi, *alo, *vhi, *vlo, *khi, *klo, *bhi, *blo;
    cudaGetSymbolAddress((void**)&qhi, g_qhi);
    cudaGetSymbolAddress((void**)&qlo, g_qlo);
    cudaGetSymbolAddress((void**)&ahi, g_ahi);
    cudaGetSymbolAddress((void**)&alo, g_alo);
    cudaGetSymbolAddress((void**)&vhi, g_vhi);
    cudaGetSymbolAddress((void**)&vlo, g_vlo);
    cudaGetSymbolAddress((void**)&khi, g_khi);
    cudaGetSymbolAddress((void**)&klo, g_klo);
    cudaGetSymbolAddress((void**)&bhi, g_bhi);
    cudaGetSymbolAddress((void**)&blo, g_blo);

    cudaFuncSetAttribute(kproj_mma,  cudaFuncAttributeMaxDynamicSharedMemorySize, KP_SMEM);
    cudaFuncSetAttribute(attn_fused, cudaFuncAttributeMaxDynamicSharedMemorySize, FS_SMEM);

    ln_q_kernel<<<B_ * NQ_, 256>>>(query, lnqw, lnqb, qpos, qhi, qlo);
    ln_k_kernel<<<B_ * NK_, 256>>>(memory, lnkw, lnkb, mpos, vhi, vlo, ahi, alo);
    wconv_kernel<<<C_ * C_ / 1024, 256>>>(Wk, bhi, blo);
    {
        dim3 grid(C_ / 128, (B_ * NK_) / 128);
        kproj_mma<<<grid, 256, KP_SMEM>>>(ahi, alo, bhi, blo, khi, klo);
    }
    {
        dim3 grid(NQ_ / 64, H_, B_);
        attn_fused<<<grid, 256, FS_SMEM>>>(qhi, qlo, khi, klo, vhi, vlo,
                                           bias, mask, query, attn, out0);
    }
}